// round 1
// baseline (speedup 1.0000x reference)
#include <cuda_runtime.h>

typedef unsigned long long u64;

#define THREADS 256
#define PAIRS 2                         // 2 f32x2 pairs -> 4 points per thread
#define PTS_PER_BLOCK (THREADS * 2 * PAIRS)
#define HIDDEN 16
#define NLAYERS 8

// ---------- f32x2 packed-math helpers (sm_103a) ----------
__device__ __forceinline__ u64 pack2(float lo, float hi) {
    u64 r; asm("mov.b64 %0, {%1, %2};" : "=l"(r) : "f"(lo), "f"(hi)); return r;
}
__device__ __forceinline__ void unpack2(u64 a, float& lo, float& hi) {
    asm("mov.b64 {%0, %1}, %2;" : "=f"(lo), "=f"(hi) : "l"(a));
}
__device__ __forceinline__ u64 ffma2(u64 a, u64 b, u64 c) {
    u64 d; asm("fma.rn.f32x2 %0, %1, %2, %3;" : "=l"(d) : "l"(a), "l"(b), "l"(c)); return d;
}
__device__ __forceinline__ u64 fmul2(u64 a, u64 b) {
    u64 d; asm("mul.rn.f32x2 %0, %1, %2;" : "=l"(d) : "l"(a), "l"(b)); return d;
}
__device__ __forceinline__ u64 fadd2(u64 a, u64 b) {
    u64 d; asm("add.rn.f32x2 %0, %1, %2;" : "=l"(d) : "l"(a), "l"(b)); return d;
}
__device__ __forceinline__ float ex2f(float x) {
    float r; asm("ex2.approx.f32 %0, %1;" : "=f"(r) : "f"(x)); return r;
}
__device__ __forceinline__ float rcpf(float x) {
    float r; asm("rcp.approx.f32 %0, %1;" : "=f"(r) : "f"(x)); return r;
}

// tanh(x) = 1 - 2/(exp(2x)+1);  exp(2x) = 2^(x * 2*log2(e))
// ex2.approx/rcp.approx rel err ~2^-22 -> ~1e-7 absolute error per tanh.
__device__ __forceinline__ u64 tanh2(u64 a) {
    const float kS = 2.8853900817779268f;  // 2*log2(e)
    u64 cS   = pack2(kS, kS);
    u64 cOne = pack2(1.0f, 1.0f);
    u64 cM2  = pack2(-2.0f, -2.0f);
    u64 m = fmul2(a, cS);
    float m0, m1; unpack2(m, m0, m1);
    u64 e = pack2(ex2f(m0), ex2f(m1));
    u64 s = fadd2(e, cOne);
    float s0, s1; unpack2(s, s0, s1);
    u64 r = pack2(rcpf(s0), rcpf(s1));
    return ffma2(cM2, r, cOne);           // 1 - 2*r
}

// sigmoid(x) = 1/(1 + exp(-x));  exp(-x) = 2^(-x*log2(e)). Returns 2 scalars.
__device__ __forceinline__ void sigmoid2(u64 a, float& o0, float& o1) {
    const float kS = -1.4426950408889634f; // -log2(e)
    u64 cS   = pack2(kS, kS);
    u64 cOne = pack2(1.0f, 1.0f);
    u64 m = fmul2(a, cS);
    float m0, m1; unpack2(m, m0, m1);
    u64 e = pack2(ex2f(m0), ex2f(m1));
    u64 s = fadd2(e, cOne);
    float s0, s1; unpack2(s, s0, s1);
    o0 = rcpf(s0); o1 = rcpf(s1);
}

__global__ void __launch_bounds__(THREADS)
mlp_kernel(const float* __restrict__ x,
           const float* __restrict__ W_in,
           const float* __restrict__ b_in,
           const float* __restrict__ W_h,
           const float* __restrict__ W_out,
           float* __restrict__ out)
{
    // Weights duplicated into both f32x2 lanes -> one broadcast LDS.64 feeds 2 FFMA2.
    __shared__ u64 sWin[HIDDEN * 2];            // [j*2 + c]
    __shared__ u64 sBin[HIDDEN];
    __shared__ u64 sWh[NLAYERS * HIDDEN * HIDDEN]; // [l*256 + j*16 + k]
    __shared__ u64 sWout[3 * HIDDEN];

    const int tid = threadIdx.x;

    if (tid < 32)            { float w = W_in[tid];        sWin[tid]       = pack2(w, w); }
    else if (tid < 48)       { float w = b_in[tid - 32];   sBin[tid - 32]  = pack2(w, w); }
    else if (tid < 96)       { float w = W_out[tid - 48];  sWout[tid - 48] = pack2(w, w); }
    #pragma unroll
    for (int i = tid; i < NLAYERS * 256; i += THREADS) {
        float w = W_h[i]; sWh[i] = pack2(w, w);
    }
    __syncthreads();

    const int base = blockIdx.x * PTS_PER_BLOCK + tid;   // point index of p=0

    // Coalesced float2 loads of x, then pack pairs (p0,p1) and (p2,p3).
    const float2* __restrict__ xp = (const float2*)x;
    float2 xv[4];
    #pragma unroll
    for (int p = 0; p < 4; p++) xv[p] = xp[base + p * THREADS];

    u64 px0[PAIRS], px1[PAIRS];
    #pragma unroll
    for (int q = 0; q < PAIRS; q++) {
        px0[q] = pack2(xv[2 * q].x, xv[2 * q + 1].x);
        px1[q] = pack2(xv[2 * q].y, xv[2 * q + 1].y);
    }

    // ---- input layer: h = tanh(x @ W_in^T + b_in) ----
    u64 h[PAIRS][HIDDEN];
    #pragma unroll
    for (int j = 0; j < HIDDEN; j++) {
        u64 w0 = sWin[2 * j], w1 = sWin[2 * j + 1], b = sBin[j];
        #pragma unroll
        for (int q = 0; q < PAIRS; q++) {
            u64 a = ffma2(px0[q], w0, b);
            a = ffma2(px1[q], w1, a);
            h[q][j] = tanh2(a);
        }
    }

    // ---- 8 hidden layers: h = tanh(h @ W^T) ----
    #pragma unroll 1
    for (int l = 0; l < NLAYERS; l++) {
        const u64* __restrict__ w = &sWh[l * 256];
        u64 acc[PAIRS][HIDDEN];
        #pragma unroll
        for (int j = 0; j < HIDDEN; j++) {
            u64 w0 = w[j * 16];
            acc[0][j] = fmul2(h[0][0], w0);
            acc[1][j] = fmul2(h[1][0], w0);
            #pragma unroll
            for (int k = 1; k < HIDDEN; k++) {
                u64 wk = w[j * 16 + k];
                acc[0][j] = ffma2(h[0][k], wk, acc[0][j]);
                acc[1][j] = ffma2(h[1][k], wk, acc[1][j]);
            }
        }
        #pragma unroll
        for (int j = 0; j < HIDDEN; j++) {
            h[0][j] = tanh2(acc[0][j]);
            h[1][j] = tanh2(acc[1][j]);
        }
    }

    // ---- output layer: sigmoid(h @ W_out^T), 16 -> 3 ----
    float o[PAIRS * 2][3];
    #pragma unroll
    for (int j = 0; j < 3; j++) {
        #pragma unroll
        for (int q = 0; q < PAIRS; q++) {
            u64 acc = fmul2(h[q][0], sWout[j * 16]);
            #pragma unroll
            for (int k = 1; k < HIDDEN; k++)
                acc = ffma2(h[q][k], sWout[j * 16 + k], acc);
            sigmoid2(acc, o[2 * q][j], o[2 * q + 1][j]);
        }
    }

    #pragma unroll
    for (int p = 0; p < 4; p++) {
        int pt = base + p * THREADS;
        out[pt * 3 + 0] = o[p][0];
        out[pt * 3 + 1] = o[p][1];
        out[pt * 3 + 2] = o[p][2];
    }
}

extern "C" void kernel_launch(void* const* d_in, const int* in_sizes, int n_in,
                              void* d_out, int out_size) {
    const float* x     = (const float*)d_in[0];
    const float* W_in  = (const float*)d_in[1];
    const float* b_in  = (const float*)d_in[2];
    const float* W_h   = (const float*)d_in[3];
    const float* W_out = (const float*)d_in[4];
    float* out = (float*)d_out;

    int n_points = in_sizes[0] / 2;               // x is [N,2]
    int blocks = n_points / PTS_PER_BLOCK;        // 4194304 / 1024 = 4096, exact
    mlp_kernel<<<blocks, THREADS>>>(x, W_in, b_in, W_h, W_out, out);
}

// round 2
// speedup vs baseline: 1.6155x; 1.6155x over previous
#include <cuda_runtime.h>

typedef unsigned long long u64;

#define THREADS 128
#define PAIRS 2                         // 2 f32x2 pairs -> 4 points per thread
#define PTS_PER_BLOCK (THREADS * 2 * PAIRS)
#define HIDDEN 16
#define NLAYERS 8

// ---------- f32x2 packed-math helpers (sm_103a) ----------
__device__ __forceinline__ u64 pack2(float lo, float hi) {
    u64 r; asm("mov.b64 %0, {%1, %2};" : "=l"(r) : "f"(lo), "f"(hi)); return r;
}
__device__ __forceinline__ void unpack2(u64 a, float& lo, float& hi) {
    asm("mov.b64 {%0, %1}, %2;" : "=f"(lo), "=f"(hi) : "l"(a));
}
__device__ __forceinline__ u64 ffma2(u64 a, u64 b, u64 c) {
    u64 d; asm("fma.rn.f32x2 %0, %1, %2, %3;" : "=l"(d) : "l"(a), "l"(b), "l"(c)); return d;
}
__device__ __forceinline__ u64 fmul2(u64 a, u64 b) {
    u64 d; asm("mul.rn.f32x2 %0, %1, %2;" : "=l"(d) : "l"(a), "l"(b)); return d;
}
__device__ __forceinline__ float tanh_hw(float x) {
    float r; asm("tanh.approx.f32 %0, %1;" : "=f"(r) : "f"(x)); return r;
}
// Packed tanh via 2x HW MUFU tanh. pack/unpack resolve to register-pair
// aliasing in SASS when allocation cooperates (no real MOVs).
__device__ __forceinline__ u64 tanh2(u64 a) {
    float lo, hi; unpack2(a, lo, hi);
    return pack2(tanh_hw(lo), tanh_hw(hi));
}
// sigmoid(x) = 0.5*tanh(0.5x) + 0.5
__device__ __forceinline__ u64 sigmoid2(u64 a) {
    u64 cH = pack2(0.5f, 0.5f);
    u64 t = tanh2(fmul2(a, cH));
    return ffma2(t, cH, cH);
}

__global__ void __launch_bounds__(THREADS, 3)
mlp_kernel(const float* __restrict__ x,
           const float* __restrict__ W_in,
           const float* __restrict__ b_in,
           const float* __restrict__ W_h,
           const float* __restrict__ W_out,
           float* __restrict__ out)
{
    // Weights duplicated into both f32x2 lanes -> one broadcast LDS feeds 2 FFMA2.
    // 16B-aligned so consecutive weight pairs load as one LDS.128.
    __shared__ __align__(16) u64 sWin[HIDDEN * 2];             // [j*2 + c]
    __shared__ __align__(16) u64 sBin[HIDDEN];
    __shared__ __align__(16) u64 sWh[NLAYERS * HIDDEN * HIDDEN]; // [l*256 + j*16 + k]
    __shared__ __align__(16) u64 sWout[4 * HIDDEN];            // padded row 4 unused

    const int tid = threadIdx.x;

    if (tid < 32)            { float w = W_in[tid];        sWin[tid]       = pack2(w, w); }
    else if (tid < 48)       { float w = b_in[tid - 32];   sBin[tid - 32]  = pack2(w, w); }
    else if (tid < 96)       { float w = W_out[tid - 48];  sWout[tid - 48] = pack2(w, w); }
    #pragma unroll
    for (int i = tid; i < NLAYERS * 256; i += THREADS) {
        float w = W_h[i]; sWh[i] = pack2(w, w);
    }
    __syncthreads();

    const int base = blockIdx.x * PTS_PER_BLOCK + tid;   // point index of p=0

    // Coalesced float2 loads of x, then pack pairs (p0,p1) and (p2,p3).
    const float2* __restrict__ xp = (const float2*)x;
    float2 xv[4];
    #pragma unroll
    for (int p = 0; p < 4; p++) xv[p] = xp[base + p * THREADS];

    u64 px0[PAIRS], px1[PAIRS];
    #pragma unroll
    for (int q = 0; q < PAIRS; q++) {
        px0[q] = pack2(xv[2 * q].x, xv[2 * q + 1].x);
        px1[q] = pack2(xv[2 * q].y, xv[2 * q + 1].y);
    }

    // ---- input layer: h = tanh(x @ W_in^T + b_in) ----
    u64 h[PAIRS][HIDDEN];
    #pragma unroll
    for (int j = 0; j < HIDDEN; j++) {
        u64 w0 = sWin[2 * j], w1 = sWin[2 * j + 1], b = sBin[j];
        #pragma unroll
        for (int q = 0; q < PAIRS; q++) {
            u64 a = ffma2(px0[q], w0, b);
            a = ffma2(px1[q], w1, a);
            h[q][j] = tanh2(a);
        }
    }

    // ---- 8 hidden layers: h = tanh(h @ W^T) ----
    #pragma unroll 1
    for (int l = 0; l < NLAYERS; l++) {
        const u64* __restrict__ w = &sWh[l * 256];
        u64 acc[PAIRS][HIDDEN];
        #pragma unroll
        for (int j = 0; j < HIDDEN; j++) {
            const ulonglong2* __restrict__ wr = (const ulonglong2*)&w[j * 16];
            ulonglong2 w01 = wr[0];
            acc[0][j] = fmul2(h[0][0], w01.x);
            acc[1][j] = fmul2(h[1][0], w01.x);
            acc[0][j] = ffma2(h[0][1], w01.y, acc[0][j]);
            acc[1][j] = ffma2(h[1][1], w01.y, acc[1][j]);
            #pragma unroll
            for (int kk = 1; kk < HIDDEN / 2; kk++) {
                ulonglong2 wk = wr[kk];
                int k = 2 * kk;
                acc[0][j] = ffma2(h[0][k], wk.x, acc[0][j]);
                acc[1][j] = ffma2(h[1][k], wk.x, acc[1][j]);
                acc[0][j] = ffma2(h[0][k + 1], wk.y, acc[0][j]);
                acc[1][j] = ffma2(h[1][k + 1], wk.y, acc[1][j]);
            }
        }
        #pragma unroll
        for (int j = 0; j < HIDDEN; j++) {
            h[0][j] = tanh2(acc[0][j]);
            h[1][j] = tanh2(acc[1][j]);
        }
    }

    // ---- output layer: sigmoid(h @ W_out^T), 16 -> 3 ----
    float o[PAIRS * 2][3];
    #pragma unroll
    for (int j = 0; j < 3; j++) {
        const ulonglong2* __restrict__ wr = (const ulonglong2*)&sWout[j * 16];
        #pragma unroll
        for (int q = 0; q < PAIRS; q++) {
            ulonglong2 w01 = wr[0];
            u64 acc = fmul2(h[q][0], w01.x);
            acc = ffma2(h[q][1], w01.y, acc);
            #pragma unroll
            for (int kk = 1; kk < HIDDEN / 2; kk++) {
                ulonglong2 wk = wr[kk];
                acc = ffma2(h[q][2 * kk], wk.x, acc);
                acc = ffma2(h[q][2 * kk + 1], wk.y, acc);
            }
            u64 s = sigmoid2(acc);
            unpack2(s, o[2 * q][j], o[2 * q + 1][j]);
        }
    }

    #pragma unroll
    for (int p = 0; p < 4; p++) {
        int pt = base + p * THREADS;
        out[pt * 3 + 0] = o[p][0];
        out[pt * 3 + 1] = o[p][1];
        out[pt * 3 + 2] = o[p][2];
    }
}

extern "C" void kernel_launch(void* const* d_in, const int* in_sizes, int n_in,
                              void* d_out, int out_size) {
    const float* x     = (const float*)d_in[0];
    const float* W_in  = (const float*)d_in[1];
    const float* b_in  = (const float*)d_in[2];
    const float* W_h   = (const float*)d_in[3];
    const float* W_out = (const float*)d_in[4];
    float* out = (float*)d_out;

    int n_points = in_sizes[0] / 2;               // x is [N,2]
    int blocks = n_points / PTS_PER_BLOCK;        // 4194304 / 512 = 8192, exact
    mlp_kernel<<<blocks, THREADS>>>(x, W_in, b_in, W_h, W_out, out);
}

// round 3
// speedup vs baseline: 1.7390x; 1.0765x over previous
#include <cuda_runtime.h>

typedef unsigned long long u64;

#define THREADS 128
#define NPTS 4                          // points per thread
#define PTS_PER_BLOCK (THREADS * NPTS)
#define HIDDEN 16
#define NLAYERS 8

// ---------- f32x2 packed-math helpers (sm_103a) ----------
__device__ __forceinline__ void unpack2(u64 a, float& lo, float& hi) {
    asm("mov.b64 {%0, %1}, %2;" : "=f"(lo), "=f"(hi) : "l"(a));
}
__device__ __forceinline__ u64 dup2(float s) {  // (s, s)
    u64 r; asm("mov.b64 %0, {%1, %1};" : "=l"(r) : "f"(s)); return r;
}
__device__ __forceinline__ u64 ffma2(u64 a, u64 b, u64 c) {
    u64 d; asm("fma.rn.f32x2 %0, %1, %2, %3;" : "=l"(d) : "l"(a), "l"(b), "l"(c)); return d;
}
__device__ __forceinline__ u64 fmul2(u64 a, u64 b) {
    u64 d; asm("mul.rn.f32x2 %0, %1, %2;" : "=l"(d) : "l"(a), "l"(b)); return d;
}
__device__ __forceinline__ float tanh_hw(float x) {
    float r; asm("tanh.approx.f32 %0, %1;" : "=f"(r) : "f"(x)); return r;
}
__device__ __forceinline__ float sigmoid_hw(float x) {
    // sigmoid(x) = 0.5*tanh(0.5x)+0.5
    return fmaf(tanh_hw(0.5f * x), 0.5f, 0.5f);
}

__global__ void __launch_bounds__(THREADS, 3)
mlp_kernel(const float* __restrict__ x,
           const float* __restrict__ W_in,
           const float* __restrict__ b_in,
           const float* __restrict__ W_h,
           const float* __restrict__ W_out,
           float* __restrict__ out)
{
    // Transposed weights, plain f32 (no lane duplication). u64 reads give
    // natural (W[j][k], W[j+1][k]) output-pairs. All reads are warp-broadcast.
    __shared__ __align__(16) float sWh_t[NLAYERS * HIDDEN * HIDDEN]; // [l][k][j]
    __shared__ __align__(16) float sWin_t[2 * HIDDEN];               // [c][j]
    __shared__ __align__(16) float sBin[HIDDEN];                     // [j]
    __shared__ __align__(16) float sWout_t[HIDDEN * 4];              // [k][j], j=3 pad 0

    const int tid = threadIdx.x;

    #pragma unroll
    for (int i = tid; i < NLAYERS * 256; i += THREADS) {
        int l = i >> 8, r = i & 255, j = r >> 4, k = r & 15;
        sWh_t[(l * 16 + k) * 16 + j] = W_h[i];      // i = l*256 + j*16 + k
    }
    if (tid < 32)      { int j = tid >> 1, c = tid & 1; sWin_t[c * 16 + j] = W_in[j * 2 + c]; }
    else if (tid < 48) { sBin[tid - 32] = b_in[tid - 32]; }
    else if (tid < 112){ int i = tid - 48; int k = i >> 2, j = i & 3;
                         sWout_t[i] = (j < 3) ? W_out[j * 16 + k] : 0.0f; }
    __syncthreads();

    const int base = blockIdx.x * PTS_PER_BLOCK + tid;

    const float2* __restrict__ xp = (const float2*)x;
    float2 xv[NPTS];
    #pragma unroll
    for (int p = 0; p < NPTS; p++) xv[p] = xp[base + p * THREADS];

    // ---- input layer: acc[p][jj] accumulates outputs (2j, 2j+1) ----
    float h[NPTS][HIDDEN];
    {
        const u64* __restrict__ w0 = (const u64*)&sWin_t[0];
        const u64* __restrict__ w1 = (const u64*)&sWin_t[16];
        const u64* __restrict__ bb = (const u64*)&sBin[0];
        #pragma unroll
        for (int p = 0; p < NPTS; p++) {
            u64 x0 = dup2(xv[p].x), x1 = dup2(xv[p].y);
            #pragma unroll
            for (int jj = 0; jj < 8; jj++) {
                u64 a = ffma2(x0, w0[jj], bb[jj]);
                a = ffma2(x1, w1[jj], a);
                float t0, t1; unpack2(a, t0, t1);
                h[p][2 * jj]     = tanh_hw(t0);
                h[p][2 * jj + 1] = tanh_hw(t1);
            }
        }
    }

    // ---- 8 hidden layers ----
    #pragma unroll 1
    for (int l = 0; l < NLAYERS; l++) {
        const float* __restrict__ wl = &sWh_t[l * 256];
        u64 acc[NPTS][8];
        // k = 0
        {
            const u64* __restrict__ wr = (const u64*)wl;
            u64 w[8];
            #pragma unroll
            for (int jj = 0; jj < 8; jj++) w[jj] = wr[jj];
            #pragma unroll
            for (int p = 0; p < NPTS; p++) {
                u64 hd = dup2(h[p][0]);
                #pragma unroll
                for (int jj = 0; jj < 8; jj++) acc[p][jj] = fmul2(hd, w[jj]);
            }
        }
        #pragma unroll
        for (int k = 1; k < HIDDEN; k++) {
            const u64* __restrict__ wr = (const u64*)(wl + k * 16);
            u64 w[8];
            #pragma unroll
            for (int jj = 0; jj < 8; jj++) w[jj] = wr[jj];
            #pragma unroll
            for (int p = 0; p < NPTS; p++) {
                u64 hd = dup2(h[p][k]);
                #pragma unroll
                for (int jj = 0; jj < 8; jj++) acc[p][jj] = ffma2(hd, w[jj], acc[p][jj]);
            }
        }
        #pragma unroll
        for (int p = 0; p < NPTS; p++) {
            #pragma unroll
            for (int jj = 0; jj < 8; jj++) {
                float t0, t1; unpack2(acc[p][jj], t0, t1);
                h[p][2 * jj]     = tanh_hw(t0);
                h[p][2 * jj + 1] = tanh_hw(t1);
            }
        }
    }

    // ---- output layer: 16 -> 3 (padded to 4), sigmoid ----
    float o[NPTS][3];
    {
        u64 acc0[NPTS], acc1[NPTS];
        {
            const u64* __restrict__ wr = (const u64*)&sWout_t[0];
            u64 wa = wr[0], wb = wr[1];
            #pragma unroll
            for (int p = 0; p < NPTS; p++) {
                u64 hd = dup2(h[p][0]);
                acc0[p] = fmul2(hd, wa);
                acc1[p] = fmul2(hd, wb);
            }
        }
        #pragma unroll
        for (int k = 1; k < HIDDEN; k++) {
            const u64* __restrict__ wr = (const u64*)&sWout_t[k * 4];
            u64 wa = wr[0], wb = wr[1];
            #pragma unroll
            for (int p = 0; p < NPTS; p++) {
                u64 hd = dup2(h[p][k]);
                acc0[p] = ffma2(hd, wa, acc0[p]);
                acc1[p] = ffma2(hd, wb, acc1[p]);
            }
        }
        #pragma unroll
        for (int p = 0; p < NPTS; p++) {
            float a0, a1, a2, a3;
            unpack2(acc0[p], a0, a1);
            unpack2(acc1[p], a2, a3);
            o[p][0] = sigmoid_hw(a0);
            o[p][1] = sigmoid_hw(a1);
            o[p][2] = sigmoid_hw(a2);
        }
    }

    #pragma unroll
    for (int p = 0; p < NPTS; p++) {
        int pt = base + p * THREADS;
        out[pt * 3 + 0] = o[p][0];
        out[pt * 3 + 1] = o[p][1];
        out[pt * 3 + 2] = o[p][2];
    }
}

extern "C" void kernel_launch(void* const* d_in, const int* in_sizes, int n_in,
                              void* d_out, int out_size) {
    const float* x     = (const float*)d_in[0];
    const float* W_in  = (const float*)d_in[1];
    const float* b_in  = (const float*)d_in[2];
    const float* W_h   = (const float*)d_in[3];
    const float* W_out = (const float*)d_in[4];
    float* out = (float*)d_out;

    int n_points = in_sizes[0] / 2;               // x is [N,2]
    int blocks = n_points / PTS_PER_BLOCK;        // 4194304 / 512 = 8192, exact
    mlp_kernel<<<blocks, THREADS>>>(x, W_in, b_in, W_h, W_out, out);
}